// round 16
// baseline (speedup 1.0000x reference)
#include <cuda_runtime.h>

#define CIN   64
#define PW    38            // padded width (32 + 2*3)
#define NPIX  1024          // 32*32
#define NPAD  (PW*PW)       // 1444

#define PLANES_BYTES (4*NPAD*16)                     // ktA,ktB,vtA,vtB = 92416
#define ATTN_SMEM    (PLANES_BYTES + 256)            // + rels

typedef unsigned long long ull;

// qkv scratch, plane index = b*8+g (256 planes of 1024 px), 16B granules.
// 6 x 4MB = 24MB, L2-resident (126MB L2).
__device__ ulonglong2 g_qA[256*NPIX];
__device__ ulonglong2 g_qB[256*NPIX];
__device__ ulonglong2 g_kA[256*NPIX];
__device__ ulonglong2 g_kB[256*NPIX];
__device__ ulonglong2 g_vA[256*NPIX];
__device__ ulonglong2 g_vB[256*NPIX];

__device__ __forceinline__ ull ffma2(ull a, ull b, ull c) {
    ull d;
    asm("fma.rn.f32x2 %0, %1, %2, %3;" : "=l"(d) : "l"(a), "l"(b), "l"(c));
    return d;
}
__device__ __forceinline__ ull add2(ull a, ull b) {
    ull d;
    asm("add.rn.f32x2 %0, %1, %2;" : "=l"(d) : "l"(a), "l"(b));
    return d;
}
__device__ __forceinline__ ull pk2(float a, float b) {
    ull r;
    asm("mov.b64 %0, {%1, %2};" : "=l"(r) : "f"(a), "f"(b));
    return r;
}
__device__ __forceinline__ float2 upk2(ull v) {
    float2 t;
    asm("mov.b64 {%0, %1}, %2;" : "=f"(t.x), "=f"(t.y) : "l"(v));
    return t;
}
__device__ __forceinline__ float ex2(float s) {
    float r;
    asm("ex2.approx.ftz.f32 %0, %1;" : "=f"(r) : "f"(s));
    return r;
}

// ============================ Kernel 1: projection ============================
// One CTA per (g, b). 256 threads, each thread 4 pixels (2 passes of 2).
// Pure FFMA2 stream: 24 independent accumulators, weights broadcast from smem.
// q written pre-scaled by log2e.
__global__ __launch_bounds__(256, 2)
void proj_kernel(const float* __restrict__ x,
                 const float* __restrict__ wq,
                 const float* __restrict__ wk,
                 const float* __restrict__ wv)
{
    __shared__ float wt[1536];          // [64 ci][24]: q0-7,k0-7,v0-7

    const int g   = blockIdx.x;
    const int b   = blockIdx.y;
    const int tid = threadIdx.x;
    const int wr  = tid >> 5;
    const int w   = tid & 31;
    const int h0  = wr * 4;
    const int cg  = (b*8 + g) * NPIX;

    const float L2E = 1.4426950408889634f;
    for (int idx = tid; idx < 1536; idx += 256) {
        int ci = idx / 24, c = idx % 24;
        float v;
        if (c < 8)       v = wq[(g*8 + c)        * 64 + ci] * L2E;
        else if (c < 16) v = wk[(g*8 + (c - 8))  * 64 + ci];
        else             v = wv[(g*8 + (c - 16)) * 64 + ci];
        wt[idx] = v;
    }
    __syncthreads();

    const float* xb = x + (size_t)b * CIN * NPIX;

    #pragma unroll
    for (int pass = 0; pass < 2; pass++) {
        const int r0 = h0 + 2*pass;
        ull acc[2][12];
        #pragma unroll
        for (int e = 0; e < 2; e++)
            #pragma unroll
            for (int p = 0; p < 12; p++) acc[e][p] = 0ULL;

        #pragma unroll 8
        for (int ci = 0; ci < 64; ci++) {
            float x0 = xb[ci*NPIX + r0*32 + w];
            float x1 = xb[ci*NPIX + (r0+1)*32 + w];
            ull xp0 = pk2(x0, x0);
            ull xp1 = pk2(x1, x1);
            const ulonglong2* wrow = (const ulonglong2*)(wt + ci*24);
            #pragma unroll
            for (int p = 0; p < 6; p++) {
                ulonglong2 wv2 = wrow[p];
                acc[0][2*p]   = ffma2(xp0, wv2.x, acc[0][2*p]);
                acc[0][2*p+1] = ffma2(xp0, wv2.y, acc[0][2*p+1]);
                acc[1][2*p]   = ffma2(xp1, wv2.x, acc[1][2*p]);
                acc[1][2*p+1] = ffma2(xp1, wv2.y, acc[1][2*p+1]);
            }
        }
        #pragma unroll
        for (int e = 0; e < 2; e++) {
            const int pos = cg + (r0 + e)*32 + w;
            ulonglong2 t;
            t.x = acc[e][0];  t.y = acc[e][1];  g_qA[pos] = t;
            t.x = acc[e][2];  t.y = acc[e][3];  g_qB[pos] = t;
            t.x = acc[e][4];  t.y = acc[e][5];  g_kA[pos] = t;
            t.x = acc[e][6];  t.y = acc[e][7];  g_kB[pos] = t;
            t.x = acc[e][8];  t.y = acc[e][9];  g_vA[pos] = t;
            t.x = acc[e][10]; t.y = acc[e][11]; g_vB[pos] = t;
        }
    }
}

// ============================ Kernel 2: attention =============================
// Phase 2 body identical to the measured-best 38.9us version (bias[4][7]
// precomputed, seed in c-operand, serial score chain, ex2).
template<bool ISH>
__device__ __forceinline__ void phase2_run(
    const ulonglong2* __restrict__ ktA, const ulonglong2* __restrict__ ktB,
    const ulonglong2* __restrict__ vtA, const ulonglong2* __restrict__ vtB,
    const ull (&Q)[4][4], const float (&bias)[4][7],
    float (&Z)[4], ull (&aa)[4][4], int h0, int w)
{
    #pragma unroll
    for (int pr = 0; pr < 10; pr++) {         // padded window rows h0..h0+9
        const int rowoff = (h0 + pr)*PW + w;
        ull seed[4];
        if (ISH) {
            #pragma unroll
            for (int o = 0; o < 4; o++) {
                const int i = pr - o;
                if (i >= 0 && i < 7) seed[o] = pk2(bias[o][i], 0.f);
            }
        }
        #pragma unroll
        for (int j = 0; j < 7; j++) {
            const int off = rowoff + j;
            ulonglong2 ka = ktA[off], kb = ktB[off];
            float e[4];
            #pragma unroll
            for (int o = 0; o < 4; o++) {
                const int i = pr - o;          // tap row for output o
                if (i >= 0 && i < 7) {
                    ull c0 = ISH ? seed[o] : pk2(bias[o][j], 0.f);
                    ull s2 = ffma2(Q[o][0], ka.x,
                             ffma2(Q[o][1], ka.y,
                             ffma2(Q[o][2], kb.x,
                             ffma2(Q[o][3], kb.y, c0))));
                    float2 sf = upk2(s2);
                    e[o] = ex2(sf.x + sf.y);   // max-free softmax, log2 domain
                    Z[o] += e[o];
                }
            }
            ulonglong2 va = vtA[off], vb = vtB[off];
            #pragma unroll
            for (int o = 0; o < 4; o++) {
                const int i = pr - o;
                if (i >= 0 && i < 7) {
                    ull e2 = pk2(e[o], e[o]);
                    aa[o][0] = ffma2(e2, va.x, aa[o][0]);
                    aa[o][1] = ffma2(e2, va.y, aa[o][1]);
                    aa[o][2] = ffma2(e2, vb.x, aa[o][2]);
                    aa[o][3] = ffma2(e2, vb.y, aa[o][3]);
                }
            }
        }
    }
}

__global__ __launch_bounds__(256, 2)
void attn_kernel(const float* __restrict__ relh,
                 const float* __restrict__ relw,
                 const float* __restrict__ cval,
                 float* __restrict__ out)
{
    extern __shared__ char smem[];
    ulonglong2* ktA = (ulonglong2*)smem;
    ulonglong2* ktB = ktA + NPAD;
    ulonglong2* vtA = ktB + NPAD;
    ulonglong2* vtB = vtA + NPAD;
    float* rels = (float*)(smem + PLANES_BYTES);     // [7][8]

    const int g   = blockIdx.x;
    const int b   = blockIdx.y;
    const int tid = threadIdx.x;
    const int wr  = tid >> 5;
    const int w   = tid & 31;
    const int h0  = wr * 4;
    const int cg  = (b*8 + g) * NPIX;
    const bool isH = (g < 4);
    const float cvg = cval[g];

    if (tid < 56) {
        int i = tid >> 3, c = tid & 7;
        rels[tid] = isH ? relh[(g*8 + c)*7 + i]
                        : relw[((g - 4)*8 + c)*7 + i];
    }
    // zero ONLY the halo border of the planes (420 cells/plane)
    {
        ulonglong2 z; z.x = 0ULL; z.y = 0ULL;
        for (int idx = tid; idx < 420; idx += 256) {
            int row, col;
            if (idx < 114)      { row = idx / 38;              col = idx % 38; }
            else if (idx < 228) { int k2 = idx - 114; row = 35 + k2/38; col = k2%38; }
            else                { int k2 = idx - 228; row = 3 + k2/6;
                                  int c6 = k2 % 6;  col = (c6 < 3) ? c6 : 32 + c6; }
            int off = row*PW + col;
            ktA[off] = z; ktB[off] = z; vtA[off] = z; vtB[off] = z;
        }
    }
    // copy k/v planes from scratch into padded smem (interior cells)
    #pragma unroll
    for (int t = 0; t < 4; t++) {
        const int idx = tid + t*256;
        const int row = idx >> 5, col = idx & 31;
        const int pi  = (row + 3)*PW + (col + 3);
        const int src = cg + idx;
        ktA[pi] = g_kA[src];
        ktB[pi] = g_kB[src];
        vtA[pi] = g_vA[src];
        vtB[pi] = g_vB[src];
    }

    // load q (pre-scaled by log2e) for the 4 owned outputs
    ull Q[4][4];
    #pragma unroll
    for (int o = 0; o < 4; o++) {
        const int pos = cg + (h0 + o)*32 + w;
        ulonglong2 qa = g_qA[pos], qb = g_qB[pos];
        Q[o][0] = qa.x; Q[o][1] = qa.y;
        Q[o][2] = qb.x; Q[o][3] = qb.y;
    }
    __syncthreads();

    // bias[o][i] = q_o . rel_i (log2 domain via q scaling)
    const ulonglong2* relp = (const ulonglong2*)rels;  // [7][2]
    float bias[4][7];
    #pragma unroll
    for (int o = 0; o < 4; o++)
        #pragma unroll
        for (int i = 0; i < 7; i++) {
            ulonglong2 r01 = relp[i*2], r23 = relp[i*2 + 1];
            ull cA = ffma2(Q[o][0], r01.x, ffma2(Q[o][1], r01.y, 0ULL));
            ull cB = ffma2(Q[o][2], r23.x, ffma2(Q[o][3], r23.y, 0ULL));
            float2 df = upk2(add2(cA, cB));
            bias[o][i] = df.x + df.y;
        }

    float Z[4] = {0.f, 0.f, 0.f, 0.f};
    ull aa[4][4];
    #pragma unroll
    for (int o = 0; o < 4; o++)
        #pragma unroll
        for (int p = 0; p < 4; p++) aa[o][p] = 0ULL;

    if (isH) phase2_run<true >(ktA, ktB, vtA, vtB, Q, bias, Z, aa, h0, w);
    else     phase2_run<false>(ktA, ktB, vtA, vtB, Q, bias, Z, aa, h0, w);

    // epilogue: adaptive ring mask + normalize + store
    float* outbase = out + ((size_t)b * 64 + g * 8) * NPIX;
    #pragma unroll
    for (int o = 0; o < 4; o++) {
        const int h   = h0 + o;
        const int pos = h*32 + w;
        int r  = min(h, 31 - h);
        int lo = (h <= 31 - h) ? r : r + 1;
        int hi = 31 - r;
        float omv  = fminf(fmaxf(((float)(r - 15) + cvg*16.0f)*(1.0f/3.0f) + 1.0f,
                                 0.0f), 1.0f);
        float mval = (w >= lo && w <= hi) ? omv : 1.0f;
        float sc   = __fdividef(mval, Z[o]);

        float2 o01 = upk2(aa[o][0]), o23 = upk2(aa[o][1]);
        float2 o45 = upk2(aa[o][2]), o67 = upk2(aa[o][3]);
        outbase[0*NPIX + pos] = o01.x * sc;
        outbase[1*NPIX + pos] = o01.y * sc;
        outbase[2*NPIX + pos] = o23.x * sc;
        outbase[3*NPIX + pos] = o23.y * sc;
        outbase[4*NPIX + pos] = o45.x * sc;
        outbase[5*NPIX + pos] = o45.y * sc;
        outbase[6*NPIX + pos] = o67.x * sc;
        outbase[7*NPIX + pos] = o67.y * sc;
    }
}

extern "C" void kernel_launch(void* const* d_in, const int* in_sizes, int n_in,
                              void* d_out, int out_size)
{
    const float* x    = (const float*)d_in[0];
    const float* wq   = (const float*)d_in[1];
    const float* wk   = (const float*)d_in[2];
    const float* wv   = (const float*)d_in[3];
    const float* relh = (const float*)d_in[4];
    const float* relw = (const float*)d_in[5];
    const float* cv   = (const float*)d_in[6];
    float* out = (float*)d_out;

    cudaFuncSetAttribute(attn_kernel,
                         cudaFuncAttributeMaxDynamicSharedMemorySize, ATTN_SMEM);
    proj_kernel<<<dim3(8, 32), 256>>>(x, wq, wk, wv);
    attn_kernel<<<dim3(8, 32), 256, ATTN_SMEM>>>(relh, relw, cv, out);
}